// round 2
// baseline (speedup 1.0000x reference)
#include <cuda_runtime.h>

#define S_LEN   2048
#define BATCH   2
#define DMODEL  1024
#define NHEADS  16
#define HDIM    64

// Scratch (allocation-free rule: __device__ globals)
__device__ float g_qkv[(size_t)BATCH * S_LEN * 3 * DMODEL];  // [4096, 3072]
__device__ float g_ctx[(size_t)BATCH * S_LEN * DMODEL];      // [4096, 1024]

// ---------------------------------------------------------------------------
// SGEMM: C[M,N] = A[M,K] @ B[K,N] (+ bias[N]).  BM=BN=128, BK=16, 256 thr,
// 8x8 per-thread micro-tile, float4 global loads. M,N,K multiples of 128/16.
// ---------------------------------------------------------------------------
template <bool HAS_BIAS>
__global__ __launch_bounds__(256) void sgemm_kernel(
    const float* __restrict__ A, const float* __restrict__ B,
    const float* __restrict__ bias, float* __restrict__ C,
    int M, int N, int K)
{
    __shared__ float As[16][128];   // transposed: As[k][m]
    __shared__ float Bs[16][128];

    const int tid = threadIdx.x;
    const int tx = tid & 15;        // n direction
    const int ty = tid >> 4;        // m direction
    const int bx = blockIdx.x;      // n tile
    const int by = blockIdx.y;      // m tile

    // global-load mapping
    const int a_row = tid >> 2;            // 0..63 (and +64)
    const int a_col = (tid & 3) << 2;      // 0,4,8,12
    const int b_row = tid >> 5;            // 0..7 (and +8)
    const int b_col = (tid & 31) << 2;     // 0..124

    float acc[8][8];
#pragma unroll
    for (int i = 0; i < 8; i++)
#pragma unroll
        for (int j = 0; j < 8; j++) acc[i][j] = 0.f;

    const float* Abase = A + (size_t)(by * 128) * K;
    const float* Bbase = B + bx * 128;

    for (int k0 = 0; k0 < K; k0 += 16) {
        float4 av0 = *(const float4*)(Abase + (size_t)a_row * K + k0 + a_col);
        float4 av1 = *(const float4*)(Abase + (size_t)(a_row + 64) * K + k0 + a_col);
        float4 bv0 = *(const float4*)(Bbase + (size_t)(k0 + b_row) * N + b_col);
        float4 bv1 = *(const float4*)(Bbase + (size_t)(k0 + b_row + 8) * N + b_col);

        As[a_col + 0][a_row] = av0.x;
        As[a_col + 1][a_row] = av0.y;
        As[a_col + 2][a_row] = av0.z;
        As[a_col + 3][a_row] = av0.w;
        As[a_col + 0][a_row + 64] = av1.x;
        As[a_col + 1][a_row + 64] = av1.y;
        As[a_col + 2][a_row + 64] = av1.z;
        As[a_col + 3][a_row + 64] = av1.w;
        *(float4*)&Bs[b_row][b_col]     = bv0;
        *(float4*)&Bs[b_row + 8][b_col] = bv1;

        __syncthreads();

#pragma unroll
        for (int kk = 0; kk < 16; kk++) {
            float4 a0 = *(const float4*)&As[kk][ty * 4];
            float4 a1 = *(const float4*)&As[kk][64 + ty * 4];
            float4 b0 = *(const float4*)&Bs[kk][tx * 4];
            float4 b1 = *(const float4*)&Bs[kk][64 + tx * 4];
            float ar[8] = {a0.x, a0.y, a0.z, a0.w, a1.x, a1.y, a1.z, a1.w};
            float br[8] = {b0.x, b0.y, b0.z, b0.w, b1.x, b1.y, b1.z, b1.w};
#pragma unroll
            for (int i = 0; i < 8; i++)
#pragma unroll
                for (int j = 0; j < 8; j++)
                    acc[i][j] += ar[i] * br[j];
        }
        __syncthreads();
    }

    float4 bb0 = make_float4(0.f, 0.f, 0.f, 0.f);
    float4 bb1 = make_float4(0.f, 0.f, 0.f, 0.f);
    if (HAS_BIAS) {
        bb0 = *(const float4*)&bias[bx * 128 + tx * 4];
        bb1 = *(const float4*)&bias[bx * 128 + 64 + tx * 4];
    }

#pragma unroll
    for (int i = 0; i < 8; i++) {
        int m = by * 128 + ((i < 4) ? (ty * 4 + i) : (64 + ty * 4 + i - 4));
        float4 o0 = make_float4(acc[i][0] + bb0.x, acc[i][1] + bb0.y,
                                acc[i][2] + bb0.z, acc[i][3] + bb0.w);
        float4 o1 = make_float4(acc[i][4] + bb1.x, acc[i][5] + bb1.y,
                                acc[i][6] + bb1.z, acc[i][7] + bb1.w);
        float* crow = C + (size_t)m * N + bx * 128;
        *(float4*)&crow[tx * 4]      = o0;
        *(float4*)&crow[64 + tx * 4] = o1;
    }
}

// ---------------------------------------------------------------------------
// Causal flash attention, fp32. One CTA per (q-tile of 64 rows, head, batch).
// KV tiles of 32. Static smem (41 KB) so no dynamic-smem attribute is needed.
// qkv layout: row n = b*S + s, cols [0:D)=Q, [D:2D)=K, [2D:3D)=V; head h at
// cols h*64 within each.
// ---------------------------------------------------------------------------
#define TQ 64
#define TK 32

__global__ __launch_bounds__(256) void attn_kernel(
    const float* __restrict__ qkv, float* __restrict__ ctx)
{
    __shared__ float Qs[TQ * 64];        // [q][d], stride 64
    __shared__ float Ks[TK * 65];        // [k][d], stride 65 (pad)
    __shared__ float Vs[TK * 64];        // [k][d], stride 64
    __shared__ float Sc[TQ * 33];        // [q][k], stride 33 (pad)

    const int t = threadIdx.x;
    const int qtile = blockIdx.x;
    const int h = blockIdx.y;
    const int b = blockIdx.z;
    const int q0 = qtile * TQ;
    const int row_base = b * S_LEN;
    const float scale = 0.125f;          // 1/sqrt(64)

    // Load Q tile: 64x64 floats = 1024 float4, 4 per thread
#pragma unroll
    for (int i = 0; i < 4; i++) {
        int idx = t + i * 256;
        int row = idx >> 4;
        int col = (idx & 15) << 2;
        float4 v = *(const float4*)&qkv[(size_t)(row_base + q0 + row) * (3 * DMODEL)
                                        + h * HDIM + col];
        *(float4*)&Qs[row * 64 + col] = v;
    }

    // roles
    const int ty = t >> 4, tx = t & 15;          // score micro-tile (4 q x 2 k)
    const int qr = ty * 4, kc = tx * 2;
    const int r   = t >> 2;                      // softmax/PV: q row
    const int dgb = (t & 3) << 4;                // 16 d-dims owned

    float4 O4[4];
#pragma unroll
    for (int u = 0; u < 4; u++) O4[u] = make_float4(0.f, 0.f, 0.f, 0.f);
    float m_i = -1e30f, l_i = 0.f;

    const int ntiles = (q0 + TQ) / TK;           // causal: tiles fully <= q0+63

    for (int j = 0; j < ntiles; j++) {
        const int k0 = j * TK;
        __syncthreads();   // previous-iter readers of Ks/Vs/Sc done

        // Load K,V tiles: 32x64 each = 512 float4, 2 per thread
#pragma unroll
        for (int i = 0; i < 2; i++) {
            int idx = t + i * 256;
            int row = idx >> 4;
            int col = (idx & 15) << 2;
            size_t base = (size_t)(row_base + k0 + row) * (3 * DMODEL)
                          + DMODEL + h * HDIM + col;
            float4 kv = *(const float4*)&qkv[base];
            Ks[row * 65 + col + 0] = kv.x;
            Ks[row * 65 + col + 1] = kv.y;
            Ks[row * 65 + col + 2] = kv.z;
            Ks[row * 65 + col + 3] = kv.w;
            float4 vv = *(const float4*)&qkv[base + DMODEL];
            *(float4*)&Vs[row * 64 + col] = vv;
        }
        __syncthreads();

        // Scores: each thread 4x2 micro-tile over d=64
        float sc[4][2];
#pragma unroll
        for (int i = 0; i < 4; i++) { sc[i][0] = 0.f; sc[i][1] = 0.f; }
#pragma unroll 8
        for (int d = 0; d < 64; d++) {
            float a0 = Qs[(qr + 0) * 64 + d];
            float a1 = Qs[(qr + 1) * 64 + d];
            float a2 = Qs[(qr + 2) * 64 + d];
            float a3 = Qs[(qr + 3) * 64 + d];
            float bb0 = Ks[(kc + 0) * 65 + d];
            float bb1 = Ks[(kc + 1) * 65 + d];
            sc[0][0] += a0 * bb0;  sc[0][1] += a0 * bb1;
            sc[1][0] += a1 * bb0;  sc[1][1] += a1 * bb1;
            sc[2][0] += a2 * bb0;  sc[2][1] += a2 * bb1;
            sc[3][0] += a3 * bb0;  sc[3][1] += a3 * bb1;
        }
#pragma unroll
        for (int i = 0; i < 4; i++)
#pragma unroll
            for (int jj = 0; jj < 2; jj++) {
                int rr = qr + i, cc = kc + jj;
                float v = sc[i][jj] * scale;
                if (k0 + cc > q0 + rr) v = -1e30f;   // causal mask
                Sc[rr * 33 + cc] = v;
            }
        __syncthreads();

        // Online softmax + P@V (4 threads per q-row, each owns 16 d-dims)
        float rowmax = -1e30f;
#pragma unroll 8
        for (int c = 0; c < TK; c++) rowmax = fmaxf(rowmax, Sc[r * 33 + c]);
        float newm = fmaxf(m_i, rowmax);
        float corr = __expf(m_i - newm);
        l_i *= corr;
#pragma unroll
        for (int u = 0; u < 4; u++) {
            O4[u].x *= corr; O4[u].y *= corr; O4[u].z *= corr; O4[u].w *= corr;
        }
#pragma unroll 4
        for (int c = 0; c < TK; c++) {
            float p = __expf(Sc[r * 33 + c] - newm);
            l_i += p;
            const float4* vp = (const float4*)&Vs[c * 64 + dgb];
            float4 v0 = vp[0], v1 = vp[1], v2 = vp[2], v3 = vp[3];
            O4[0].x += p * v0.x; O4[0].y += p * v0.y; O4[0].z += p * v0.z; O4[0].w += p * v0.w;
            O4[1].x += p * v1.x; O4[1].y += p * v1.y; O4[1].z += p * v1.z; O4[1].w += p * v1.w;
            O4[2].x += p * v2.x; O4[2].y += p * v2.y; O4[2].z += p * v2.z; O4[2].w += p * v2.w;
            O4[3].x += p * v3.x; O4[3].y += p * v3.y; O4[3].z += p * v3.z; O4[3].w += p * v3.w;
        }
        m_i = newm;
    }

    const float inv = 1.0f / l_i;
    float* dst = &ctx[(size_t)(row_base + q0 + r) * DMODEL + h * HDIM + dgb];
#pragma unroll
    for (int u = 0; u < 4; u++) {
        float4 o = O4[u];
        o.x *= inv; o.y *= inv; o.z *= inv; o.w *= inv;
        *(float4*)&dst[u * 4] = o;
    }
}

// ---------------------------------------------------------------------------
extern "C" void kernel_launch(void* const* d_in, const int* in_sizes, int n_in,
                              void* d_out, int out_size)
{
    const float* x     = (const float*)d_in[0];
    const float* W_qkv = (const float*)d_in[1];
    const float* b_qkv = (const float*)d_in[2];
    const float* W_out = (const float*)d_in[3];
    float* out = (float*)d_out;

    float *qkv, *ctx;
    cudaGetSymbolAddress((void**)&qkv, g_qkv);
    cudaGetSymbolAddress((void**)&ctx, g_ctx);

    const int M = BATCH * S_LEN;          // 4096

    // 1) qkv = x @ W_qkv + b_qkv   [4096, 3072]
    sgemm_kernel<true><<<dim3((3 * DMODEL) / 128, M / 128), 256>>>(
        x, W_qkv, b_qkv, qkv, M, 3 * DMODEL, DMODEL);

    // 2) causal attention -> ctx   [4096, 1024]
    attn_kernel<<<dim3(S_LEN / TQ, NHEADS, BATCH), 256>>>(qkv, ctx);

    // 3) out = ctx @ W_out         [4096, 1024]
    sgemm_kernel<false><<<dim3(DMODEL / 128, M / 128), 256>>>(
        ctx, W_out, nullptr, out, M, DMODEL, DMODEL);
}

// round 6
// speedup vs baseline: 2.4089x; 2.4089x over previous
#include <cuda_runtime.h>
#include <cstdint>

#define S_LEN   2048
#define BATCH   2
#define DMODEL  1024
#define NHEADS  16
#define HDIM    64

// Scratch (allocation-free rule: __device__ globals)
__device__ float g_qkv[(size_t)BATCH * S_LEN * 3 * DMODEL];  // [4096, 3072]
__device__ float g_ctx[(size_t)BATCH * S_LEN * DMODEL];      // [4096, 1024]

// ---------------------------------------------------------------------------
// SGEMM (unchanged from verified baseline)
// ---------------------------------------------------------------------------
template <bool HAS_BIAS>
__global__ __launch_bounds__(256) void sgemm_kernel(
    const float* __restrict__ A, const float* __restrict__ B,
    const float* __restrict__ bias, float* __restrict__ C,
    int M, int N, int K)
{
    __shared__ float As[16][128];
    __shared__ float Bs[16][128];

    const int tid = threadIdx.x;
    const int tx = tid & 15;
    const int ty = tid >> 4;
    const int bx = blockIdx.x;
    const int by = blockIdx.y;

    const int a_row = tid >> 2;
    const int a_col = (tid & 3) << 2;
    const int b_row = tid >> 5;
    const int b_col = (tid & 31) << 2;

    float acc[8][8];
#pragma unroll
    for (int i = 0; i < 8; i++)
#pragma unroll
        for (int j = 0; j < 8; j++) acc[i][j] = 0.f;

    const float* Abase = A + (size_t)(by * 128) * K;
    const float* Bbase = B + bx * 128;

    for (int k0 = 0; k0 < K; k0 += 16) {
        float4 av0 = *(const float4*)(Abase + (size_t)a_row * K + k0 + a_col);
        float4 av1 = *(const float4*)(Abase + (size_t)(a_row + 64) * K + k0 + a_col);
        float4 bv0 = *(const float4*)(Bbase + (size_t)(k0 + b_row) * N + b_col);
        float4 bv1 = *(const float4*)(Bbase + (size_t)(k0 + b_row + 8) * N + b_col);

        As[a_col + 0][a_row] = av0.x;
        As[a_col + 1][a_row] = av0.y;
        As[a_col + 2][a_row] = av0.z;
        As[a_col + 3][a_row] = av0.w;
        As[a_col + 0][a_row + 64] = av1.x;
        As[a_col + 1][a_row + 64] = av1.y;
        As[a_col + 2][a_row + 64] = av1.z;
        As[a_col + 3][a_row + 64] = av1.w;
        *(float4*)&Bs[b_row][b_col]     = bv0;
        *(float4*)&Bs[b_row + 8][b_col] = bv1;

        __syncthreads();

#pragma unroll
        for (int kk = 0; kk < 16; kk++) {
            float4 a0 = *(const float4*)&As[kk][ty * 4];
            float4 a1 = *(const float4*)&As[kk][64 + ty * 4];
            float4 b0 = *(const float4*)&Bs[kk][tx * 4];
            float4 b1 = *(const float4*)&Bs[kk][64 + tx * 4];
            float ar[8] = {a0.x, a0.y, a0.z, a0.w, a1.x, a1.y, a1.z, a1.w};
            float br[8] = {b0.x, b0.y, b0.z, b0.w, b1.x, b1.y, b1.z, b1.w};
#pragma unroll
            for (int i = 0; i < 8; i++)
#pragma unroll
                for (int j = 0; j < 8; j++)
                    acc[i][j] += ar[i] * br[j];
        }
        __syncthreads();
    }

    float4 bb0 = make_float4(0.f, 0.f, 0.f, 0.f);
    float4 bb1 = make_float4(0.f, 0.f, 0.f, 0.f);
    if (HAS_BIAS) {
        bb0 = *(const float4*)&bias[bx * 128 + tx * 4];
        bb1 = *(const float4*)&bias[bx * 128 + 64 + tx * 4];
    }

#pragma unroll
    for (int i = 0; i < 8; i++) {
        int m = by * 128 + ((i < 4) ? (ty * 4 + i) : (64 + ty * 4 + i - 4));
        float4 o0 = make_float4(acc[i][0] + bb0.x, acc[i][1] + bb0.y,
                                acc[i][2] + bb0.z, acc[i][3] + bb0.w);
        float4 o1 = make_float4(acc[i][4] + bb1.x, acc[i][5] + bb1.y,
                                acc[i][6] + bb1.z, acc[i][7] + bb1.w);
        float* crow = C + (size_t)m * N + bx * 128;
        *(float4*)&crow[tx * 4]      = o0;
        *(float4*)&crow[64 + tx * 4] = o1;
    }
}

// ---------------------------------------------------------------------------
// TF32 tensor-core causal flash attention.
// CTA: 128 threads (4 warps), 64 q-rows per CTA (16 per warp), KV tiles of 64.
// Q resident in registers as TF32 fragments (scale folded in).
// mma.sync.m16n8k8 tf32: S = Q@K^T, O += P@V. P stays in registers
// (C->A fragment permute via quad shuffles).
// ---------------------------------------------------------------------------
#define TQ 64
#define TKV 64
#define KSTRIDE 68   // conflict-free for score B-fragment LDS
#define VSTRIDE 72   // conflict-free for PV B-fragment LDS

static __device__ __forceinline__ uint32_t f2tf32(float f) {
    uint32_t u;
    asm("cvt.rna.tf32.f32 %0, %1;" : "=r"(u) : "f"(f));
    return u;
}

static __device__ __forceinline__ void mma16n8k8(
    float& c0, float& c1, float& c2, float& c3,
    uint32_t a0, uint32_t a1, uint32_t a2, uint32_t a3,
    uint32_t b0, uint32_t b1)
{
    asm volatile(
        "mma.sync.aligned.m16n8k8.row.col.f32.tf32.tf32.f32 "
        "{%0,%1,%2,%3}, {%4,%5,%6,%7}, {%8,%9}, {%0,%1,%2,%3};\n"
        : "+f"(c0), "+f"(c1), "+f"(c2), "+f"(c3)
        : "r"(a0), "r"(a1), "r"(a2), "r"(a3), "r"(b0), "r"(b1));
}

__global__ __launch_bounds__(128) void attn_kernel(
    const float* __restrict__ qkv, float* __restrict__ ctx)
{
    __shared__ float Ks[TKV * KSTRIDE];
    __shared__ float Vs[TKV * VSTRIDE];

    const int t    = threadIdx.x;
    const int w    = t >> 5;          // warp 0..3
    const int lane = t & 31;
    const int g    = lane >> 2;       // groupID (row within fragment)
    const int q    = lane & 3;        // threadID_in_group

    // Heavy (large-qtile) CTAs first to shrink the tail wave.
    const int qt = (int)gridDim.x - 1 - (int)blockIdx.x;
    const int h  = blockIdx.y;
    const int b  = blockIdx.z;
    const int q0 = qt * TQ;
    const int rowb = b * S_LEN;

    // --- Q fragments, resident in registers, scale folded in -------------
    uint32_t qa[8][4];
    {
        const float* qp0 = qkv + (size_t)(rowb + q0 + w * 16 + g) * (3 * DMODEL) + h * HDIM;
        const float* qp8 = qp0 + (size_t)8 * (3 * DMODEL);
#pragma unroll
        for (int kc = 0; kc < 8; kc++) {
            int c = kc * 8 + q;
            qa[kc][0] = f2tf32(qp0[c]     * 0.125f);
            qa[kc][1] = f2tf32(qp8[c]     * 0.125f);
            qa[kc][2] = f2tf32(qp0[c + 4] * 0.125f);
            qa[kc][3] = f2tf32(qp8[c + 4] * 0.125f);
        }
    }

    float o[8][4];
#pragma unroll
    for (int n = 0; n < 8; n++)
#pragma unroll
        for (int i = 0; i < 4; i++) o[n][i] = 0.f;
    float m0 = -1e30f, m1 = -1e30f, l0 = 0.f, l1 = 0.f;

    const int ntiles = qt + 1;
    const int r0g = q0 + w * 16 + g;      // global q row for c0/c1
    const int r1g = r0g + 8;              // for c2/c3

    for (int j = 0; j < ntiles; j++) {
        const int k0 = j * TKV;
        __syncthreads();

        // --- stage K,V tiles (cvt to tf32 on store) -----------------------
#pragma unroll
        for (int i = 0; i < 8; i++) {
            int linear = i * 128 + t;
            int row = linear >> 4;
            int col = (linear & 15) << 2;
            size_t base = (size_t)(rowb + k0 + row) * (3 * DMODEL) + DMODEL + h * HDIM + col;
            float4 kv = *(const float4*)&qkv[base];
            float4 vv = *(const float4*)&qkv[base + DMODEL];
            float4 kt = make_float4(__uint_as_float(f2tf32(kv.x)),
                                    __uint_as_float(f2tf32(kv.y)),
                                    __uint_as_float(f2tf32(kv.z)),
                                    __uint_as_float(f2tf32(kv.w)));
            float4 vt = make_float4(__uint_as_float(f2tf32(vv.x)),
                                    __uint_as_float(f2tf32(vv.y)),
                                    __uint_as_float(f2tf32(vv.z)),
                                    __uint_as_float(f2tf32(vv.w)));
            *(float4*)&Ks[row * KSTRIDE + col] = kt;
            *(float4*)&Vs[row * VSTRIDE + col] = vt;
        }
        __syncthreads();

        // --- scores: S[16,64] = Q @ K^T ----------------------------------
        float sc[8][4];
#pragma unroll
        for (int n = 0; n < 8; n++) {
            sc[n][0] = sc[n][1] = sc[n][2] = sc[n][3] = 0.f;
#pragma unroll
            for (int kc = 0; kc < 8; kc++) {
                uint32_t b0 = __float_as_uint(Ks[(n * 8 + g) * KSTRIDE + kc * 8 + q]);
                uint32_t b1 = __float_as_uint(Ks[(n * 8 + g) * KSTRIDE + kc * 8 + q + 4]);
                mma16n8k8(sc[n][0], sc[n][1], sc[n][2], sc[n][3],
                          qa[kc][0], qa[kc][1], qa[kc][2], qa[kc][3], b0, b1);
            }
        }

        // --- causal mask (diagonal tile only) ----------------------------
        if (j == ntiles - 1) {
#pragma unroll
            for (int n = 0; n < 8; n++) {
                int c0col = k0 + n * 8 + 2 * q;
                if (c0col     > r0g) sc[n][0] = -1e30f;
                if (c0col + 1 > r0g) sc[n][1] = -1e30f;
                if (c0col     > r1g) sc[n][2] = -1e30f;
                if (c0col + 1 > r1g) sc[n][3] = -1e30f;
            }
        }

        // --- online softmax ----------------------------------------------
        float mx0 = -1e30f, mx1 = -1e30f;
#pragma unroll
        for (int n = 0; n < 8; n++) {
            mx0 = fmaxf(mx0, fmaxf(sc[n][0], sc[n][1]));
            mx1 = fmaxf(mx1, fmaxf(sc[n][2], sc[n][3]));
        }
        mx0 = fmaxf(mx0, __shfl_xor_sync(0xffffffffu, mx0, 1));
        mx0 = fmaxf(mx0, __shfl_xor_sync(0xffffffffu, mx0, 2));
        mx1 = fmaxf(mx1, __shfl_xor_sync(0xffffffffu, mx1, 1));
        mx1 = fmaxf(mx1, __shfl_xor_sync(0xffffffffu, mx1, 2));

        float nm0 = fmaxf(m0, mx0);
        float nm1 = fmaxf(m1, mx1);
        float corr0 = __expf(m0 - nm0);
        float corr1 = __expf(m1 - nm1);
        m0 = nm0; m1 = nm1;
        l0 *= corr0; l1 *= corr1;

        float s0 = 0.f, s1 = 0.f;
#pragma unroll
        for (int n = 0; n < 8; n++) {
            sc[n][0] = __expf(sc[n][0] - nm0);
            sc[n][1] = __expf(sc[n][1] - nm0);
            sc[n][2] = __expf(sc[n][2] - nm1);
            sc[n][3] = __expf(sc[n][3] - nm1);
            s0 += sc[n][0] + sc[n][1];
            s1 += sc[n][2] + sc[n][3];
        }
        s0 += __shfl_xor_sync(0xffffffffu, s0, 1);
        s0 += __shfl_xor_sync(0xffffffffu, s0, 2);
        s1 += __shfl_xor_sync(0xffffffffu, s1, 1);
        s1 += __shfl_xor_sync(0xffffffffu, s1, 2);
        l0 += s0; l1 += s1;

#pragma unroll
        for (int n = 0; n < 8; n++) {
            o[n][0] *= corr0; o[n][1] *= corr0;
            o[n][2] *= corr1; o[n][3] *= corr1;
        }

        // --- PV: O[16,64] += P @ V ---------------------------------------
        const int src1 = (lane & ~3) + (q >> 1);
        const int src2 = src1 + 2;
#pragma unroll
        for (int kc = 0; kc < 8; kc++) {
            uint32_t u0 = f2tf32(sc[kc][0]);
            uint32_t u1 = f2tf32(sc[kc][1]);
            uint32_t u2 = f2tf32(sc[kc][2]);
            uint32_t u3 = f2tf32(sc[kc][3]);
            // C-layout -> A-layout permute within the quad
            uint32_t x0 = __shfl_sync(0xffffffffu, u0, src1);
            uint32_t x1 = __shfl_sync(0xffffffffu, u1, src1);
            uint32_t x2 = __shfl_sync(0xffffffffu, u2, src1);
            uint32_t x3 = __shfl_sync(0xffffffffu, u3, src1);
            uint32_t y0 = __shfl_sync(0xffffffffu, u0, src2);
            uint32_t y1 = __shfl_sync(0xffffffffu, u1, src2);
            uint32_t y2 = __shfl_sync(0xffffffffu, u2, src2);
            uint32_t y3 = __shfl_sync(0xffffffffu, u3, src2);
            uint32_t a0 = (q & 1) ? x1 : x0;
            uint32_t a1 = (q & 1) ? x3 : x2;
            uint32_t a2 = (q & 1) ? y1 : y0;
            uint32_t a3 = (q & 1) ? y3 : y2;
#pragma unroll
            for (int n = 0; n < 8; n++) {
                uint32_t b0 = __float_as_uint(Vs[(kc * 8 + q)     * VSTRIDE + n * 8 + g]);
                uint32_t b1 = __float_as_uint(Vs[(kc * 8 + q + 4) * VSTRIDE + n * 8 + g]);
                mma16n8k8(o[n][0], o[n][1], o[n][2], o[n][3], a0, a1, a2, a3, b0, b1);
            }
        }
    }

    // --- epilogue ---------------------------------------------------------
    const float inv0 = 1.0f / l0;
    const float inv1 = 1.0f / l1;
    float* d0 = &ctx[(size_t)(rowb + r0g) * DMODEL + h * HDIM];
    float* d1 = &ctx[(size_t)(rowb + r1g) * DMODEL + h * HDIM];
#pragma unroll
    for (int n = 0; n < 8; n++) {
        int cc = n * 8 + 2 * q;
        *(float2*)&d0[cc] = make_float2(o[n][0] * inv0, o[n][1] * inv0);
        *(float2*)&d1[cc] = make_float2(o[n][2] * inv1, o[n][3] * inv1);
    }
}

// ---------------------------------------------------------------------------
extern "C" void kernel_launch(void* const* d_in, const int* in_sizes, int n_in,
                              void* d_out, int out_size)
{
    const float* x     = (const float*)d_in[0];
    const float* W_qkv = (const float*)d_in[1];
    const float* b_qkv = (const float*)d_in[2];
    const float* W_out = (const float*)d_in[3];
    float* out = (float*)d_out;

    float *qkv, *ctx;
    cudaGetSymbolAddress((void**)&qkv, g_qkv);
    cudaGetSymbolAddress((void**)&ctx, g_ctx);

    const int M = BATCH * S_LEN;          // 4096

    // 1) qkv = x @ W_qkv + b_qkv   [4096, 3072]
    sgemm_kernel<true><<<dim3((3 * DMODEL) / 128, M / 128), 256>>>(
        x, W_qkv, b_qkv, qkv, M, 3 * DMODEL, DMODEL);

    // 2) causal attention -> ctx   [4096, 1024]
    attn_kernel<<<dim3(S_LEN / TQ, NHEADS, BATCH), 128>>>(qkv, ctx);

    // 3) out = ctx @ W_out         [4096, 1024]
    sgemm_kernel<false><<<dim3(DMODEL / 128, M / 128), 256>>>(
        ctx, W_out, nullptr, out, M, DMODEL, DMODEL);
}